// round 15
// baseline (speedup 1.0000x reference)
#include <cuda_runtime.h>
#include <cuda_bf16.h>
#include <cstdint>

// ---------------------------------------------------------------------------
// SNN MLP forward — bf16 HMMA, fragment-prepacked, 16-warp GEMM.
//   Xb  = bf16(X)    binary -> exact, prepacked m16n8k16 A-fragment order
//   W1  = W1hi+W1lo  bf16 split (validated), prepacked B-fragment order
//   U1  = Xb@W1hi + Xb@W1lo   mma.sync m16n8k16, shared fp32 accumulators
//   S1  = LIF-scan(U1) + fused rare-spike scatter into U2
//   S2  = LIF-scan(U2) smem-staged
// R14 ncu: tensor 60.4%, occ 12.4% (2 warps/SMSP, regs=197) -> latency-starved.
// Fix: warp tile 64x32, 512 thr / 16 warps -> 4 warps/SMSP, ~110 regs.
// ---------------------------------------------------------------------------

#define T_STEPS  100
#define BATCH    256
#define IN_DIM   784
#define HID_DIM  1024
#define OUT_DIM  10
#define M_ROWS   25600
#define KT_TILES 50                  // K padded 784 -> 800 (49 real + 1 zero tile)
#define MT_TILES 1600
#define NT_TILES 128
#define DECAY_F  0.6f
#define THRESH_F 0.9f

// GEMM: BM=128, BN=256, BK=32 (2 k16/stage), 3 stages, 512 thr (16 warps 2m x 8n)
#define NIT      25
#define SA_OFF   0                   // A: 8KB
#define SBH_OFF  8192                // Bh: 16KB
#define SBL_OFF  24576               // Bl: 16KB
#define STAGE_BYTES 40960
#define SMEM_GEMM (3 * STAGE_BYTES)  // 122880

// Device scratch
__device__ float g_u1[(size_t)M_ROWS * HID_DIM];
__device__ float g_u2[(size_t)M_ROWS * OUT_DIM];
__device__ float g_s1[(size_t)M_ROWS * HID_DIM];
__device__ __align__(16) uint8_t g_xa[(size_t)KT_TILES * MT_TILES * 512];
__device__ __align__(16) uint8_t g_wh[(size_t)KT_TILES * NT_TILES * 256];
__device__ __align__(16) uint8_t g_wl[(size_t)KT_TILES * NT_TILES * 256];

// ---------------------------------------------------------------------------
// PTX helpers (sm_80-era only)
// ---------------------------------------------------------------------------
__device__ __forceinline__ uint32_t smem_u32(const void* p) {
    uint32_t a;
    asm("{ .reg .u64 t; cvta.to.shared.u64 t, %1; cvt.u32.u64 %0, t; }" : "=r"(a) : "l"(p));
    return a;
}
__device__ __forceinline__ void cp16(uint32_t dst, const void* src) {
    asm volatile("cp.async.cg.shared.global [%0], [%1], 16;" :: "r"(dst), "l"(src));
}
__device__ __forceinline__ void cp_commit() { asm volatile("cp.async.commit_group;" ::: "memory"); }
__device__ __forceinline__ void cp_wait2()  { asm volatile("cp.async.wait_group 2;"  ::: "memory"); }

__device__ __forceinline__ void lds128(uint32_t* r, uint32_t a) {
    asm volatile("ld.shared.v4.u32 {%0,%1,%2,%3}, [%4];"
                 : "=r"(r[0]), "=r"(r[1]), "=r"(r[2]), "=r"(r[3]) : "r"(a));
}
__device__ __forceinline__ void lds64(uint32_t* r, uint32_t a) {
    asm volatile("ld.shared.v2.u32 {%0,%1}, [%2];" : "=r"(r[0]), "=r"(r[1]) : "r"(a));
}
__device__ __forceinline__ void mma_bf16(float* c, const uint32_t* a, uint32_t b0, uint32_t b1) {
    asm volatile("mma.sync.aligned.m16n8k16.row.col.f32.bf16.bf16.f32 "
                 "{%0,%1,%2,%3}, {%4,%5,%6,%7}, {%8,%9}, {%0,%1,%2,%3};"
                 : "+f"(c[0]), "+f"(c[1]), "+f"(c[2]), "+f"(c[3])
                 : "r"(a[0]), "r"(a[1]), "r"(a[2]), "r"(a[3]), "r"(b0), "r"(b1));
}
__device__ __forceinline__ uint32_t bf16x2(float x, float y) {
    __nv_bfloat162 v = __float22bfloat162_rn(make_float2(x, y));
    return *reinterpret_cast<uint32_t*>(&v);
}

// ---------------------------------------------------------------------------
// conv_x: X fp32 -> bf16 A-fragments (tile 512B; lane 16B = a0..a3)
// ---------------------------------------------------------------------------
__device__ __forceinline__ uint32_t xpair(const float* X, int r, int c) {
    if (c >= IN_DIM) return 0u;
    float2 v = *reinterpret_cast<const float2*>(X + (size_t)r * IN_DIM + c);
    return bf16x2(v.x, v.y);
}

__global__ void conv_x_kernel(const float* __restrict__ X)
{
    int t = blockIdx.x * blockDim.x + threadIdx.x;
    if (t >= KT_TILES * MT_TILES * 32) return;
    int lane = t & 31;
    int tile = t >> 5;
    int kt = tile / MT_TILES;
    int mt = tile - kt * MT_TILES;

    int r = mt * 16 + (lane >> 2);
    int c = kt * 16 + 2 * (lane & 3);

    uint4 frag;
    frag.x = xpair(X, r,     c);
    frag.y = xpair(X, r + 8, c);
    frag.z = xpair(X, r,     c + 8);
    frag.w = xpair(X, r + 8, c + 8);
    *reinterpret_cast<uint4*>(&g_xa[(size_t)t * 16]) = frag;
}

__global__ void zero_kernel()
{
    int idx = blockIdx.x * blockDim.x + threadIdx.x;
    if (idx < M_ROWS * OUT_DIM / 4)
        reinterpret_cast<float4*>(g_u2)[idx] = make_float4(0.f, 0.f, 0.f, 0.f);
}

// ---------------------------------------------------------------------------
// conv_w: W1 -> hi/lo bf16 B-fragments (tile 256B; lane 8B = b0,b1)
// ---------------------------------------------------------------------------
__global__ void conv_w_kernel(const float* __restrict__ W1)
{
    int t = blockIdx.x * blockDim.x + threadIdx.x;
    if (t >= KT_TILES * NT_TILES * 32) return;
    int lane = t & 31;
    int tile = t >> 5;
    int kt = tile >> 7;
    int nt = tile & 127;

    int n = nt * 8 + (lane >> 2);
    int k = kt * 16 + 2 * (lane & 3);

    float w[4];
#pragma unroll
    for (int j = 0; j < 4; j++) {
        int kk = k + (j >> 1) * 8 + (j & 1);          // k, k+1, k+8, k+9
        w[j] = (kk < IN_DIM) ? W1[(size_t)kk * HID_DIM + n] : 0.f;
    }
    float hi[4], lo[4];
#pragma unroll
    for (int j = 0; j < 4; j++) {
        hi[j] = __bfloat162float(__float2bfloat16_rn(w[j]));
        lo[j] = w[j] - hi[j];
    }
    *reinterpret_cast<uint2*>(&g_wh[(size_t)t * 8]) =
        make_uint2(bf16x2(hi[0], hi[1]), bf16x2(hi[2], hi[3]));
    *reinterpret_cast<uint2*>(&g_wl[(size_t)t * 8]) =
        make_uint2(bf16x2(lo[0], lo[1]), bf16x2(lo[2], lo[3]));
}

// ---------------------------------------------------------------------------
// GEMM1: 512 thr, 16 warps (2m x 8n), warp tile 64x32; BM=128 BN=256 BK=32.
// ---------------------------------------------------------------------------
__global__ void __launch_bounds__(512, 1)
gemm1_kernel()
{
    extern __shared__ char smem[];
    const uint32_t sb = smem_u32(smem);
    const int tid  = threadIdx.x;
    const int lane = tid & 31;
    const int w    = tid >> 5;
    const int wm   = w >> 3;           // 0..1  (m: 64 rows)
    const int wn   = w & 7;            // 0..7  (n: 32 cols)
    const int bx   = blockIdx.x;       // 0..3
    const int by   = blockIdx.y;       // 0..199

    auto load_stage = [&](int it, int s) {
        uint32_t st = sb + (uint32_t)s * STAGE_BYTES;
        // A: 8KB = 512 cp16, one per thread
        {
            int ktl = tid >> 8;
            int rem = tid & 255;                   // mt_local*32 + lane
            cp16(st + SA_OFF + (uint32_t)tid * 16,
                 g_xa + ((size_t)(it * 2 + ktl) * MT_TILES + by * 8 + (rem >> 5)) * 512
                      + (rem & 31) * 16);
        }
        // B planes: 16KB each = 1024 cp16 -> 2 per thread per plane
#pragma unroll
        for (int h = 0; h < 2; h++) {
            int id  = tid + h * 512;               // 0..1023
            int ktl = id >> 9;
            int rem = id & 511;                    // nt_local*16 + chunk
            size_t src = ((size_t)(it * 2 + ktl) * NT_TILES + bx * 32 + (rem >> 4)) * 256
                         + (rem & 15) * 16;
            uint32_t dst = (uint32_t)id * 16;
            cp16(st + SBH_OFF + dst, g_wh + src);
            cp16(st + SBL_OFF + dst, g_wl + src);
        }
    };

    float acc[4][4][4];
#pragma unroll
    for (int i = 0; i < 4; i++)
#pragma unroll
        for (int j = 0; j < 4; j++)
#pragma unroll
            for (int q = 0; q < 4; q++) acc[i][j][q] = 0.f;

    load_stage(0, 0); cp_commit();
    load_stage(1, 1); cp_commit();

    for (int it = 0; it < NIT; it++) {
        __syncthreads();                           // buffer (it%3) about to be reused
        if (it + 2 < NIT) load_stage(it + 2, (it + 2) % 3);
        cp_commit();                               // tail empty groups keep count aligned
        cp_wait2();                                // stage 'it' resident
        __syncthreads();

        const uint32_t st = sb + (uint32_t)(it % 3) * STAGE_BYTES;
#pragma unroll
        for (int ktl = 0; ktl < 2; ktl++) {
            uint32_t a[4][4];
#pragma unroll
            for (int i = 0; i < 4; i++)
                lds128(a[i], st + SA_OFF +
                       (uint32_t)(ktl * 4096 + (wm * 4 + i) * 512 + lane * 16));
#pragma unroll
            for (int j = 0; j < 4; j++) {          // hi plane
                uint32_t b[2];
                lds64(b, st + SBH_OFF +
                      (uint32_t)(ktl * 8192 + (wn * 4 + j) * 256 + lane * 8));
#pragma unroll
                for (int i = 0; i < 4; i++) mma_bf16(acc[i][j], a[i], b[0], b[1]);
            }
#pragma unroll
            for (int j = 0; j < 4; j++) {          // lo plane, same accumulators
                uint32_t b[2];
                lds64(b, st + SBL_OFF +
                      (uint32_t)(ktl * 8192 + (wn * 4 + j) * 256 + lane * 8));
#pragma unroll
                for (int i = 0; i < 4; i++) mma_bf16(acc[i][j], a[i], b[0], b[1]);
            }
        }
    }

    // Epilogue
    const int row0 = by * 128 + wm * 64 + (lane >> 2);
    const int col0 = bx * 256 + wn * 32 + 2 * (lane & 3);
#pragma unroll
    for (int i = 0; i < 4; i++) {
#pragma unroll
        for (int j = 0; j < 4; j++) {
            float* p0 = g_u1 + (size_t)(row0 + i * 16)     * HID_DIM + col0 + j * 8;
            float* p1 = g_u1 + (size_t)(row0 + i * 16 + 8) * HID_DIM + col0 + j * 8;
            *reinterpret_cast<float2*>(p0) = make_float2(acc[i][j][0], acc[i][j][1]);
            *reinterpret_cast<float2*>(p1) = make_float2(acc[i][j][2], acc[i][j][3]);
        }
    }
}

// ---------------------------------------------------------------------------
// lif1 (float4, 4 chains/thread) + fused rare-spike scatter into U2
// ---------------------------------------------------------------------------
__global__ void lif1_kernel(float* __restrict__ Sdst, const float* __restrict__ W2)
{
    const int t4 = (blockIdx.x * blockDim.x + threadIdx.x) * 4;
    if (t4 >= BATCH * HID_DIM) return;
    const int b  = t4 >> 10;
    const int h0 = t4 & 1023;
    const size_t stride = (size_t)BATCH * HID_DIM;

    float m0 = 0.f, m1 = 0.f, m2 = 0.f, m3 = 0.f;
    for (int t = 0; t < T_STEPS; t++) {
        float4 u = *reinterpret_cast<const float4*>(g_u1 + (size_t)t * stride + t4);
        m0 = m0 * DECAY_F + u.x;  m1 = m1 * DECAY_F + u.y;
        m2 = m2 * DECAY_F + u.z;  m3 = m3 * DECAY_F + u.w;
        float s0 = (m0 >= THRESH_F) ? 1.f : 0.f;
        float s1 = (m1 >= THRESH_F) ? 1.f : 0.f;
        float s2 = (m2 >= THRESH_F) ? 1.f : 0.f;
        float s3 = (m3 >= THRESH_F) ? 1.f : 0.f;
        m0 -= s0 * THRESH_F; m1 -= s1 * THRESH_F;
        m2 -= s2 * THRESH_F; m3 -= s3 * THRESH_F;
        *reinterpret_cast<float4*>(Sdst + (size_t)t * stride + t4) =
            make_float4(s0, s1, s2, s3);
        if (s0 + s1 + s2 + s3 != 0.f) {
            float* u2 = g_u2 + (size_t)t * BATCH * OUT_DIM + (size_t)b * OUT_DIM;
            float sv[4] = {s0, s1, s2, s3};
#pragma unroll
            for (int c = 0; c < 4; c++) {
                if (sv[c] != 0.f) {
                    const float* wr = W2 + (size_t)(h0 + c) * OUT_DIM;
#pragma unroll
                    for (int o = 0; o < OUT_DIM; o++) atomicAdd(u2 + o, wr[o]);
                }
            }
        }
    }
}

// ---------------------------------------------------------------------------
// lif2: smem-staged scan
// ---------------------------------------------------------------------------
__global__ void lif2_kernel(float* __restrict__ Odst)
{
    extern __shared__ float su[];
    const int c0 = blockIdx.x * 256;
    const int tid = threadIdx.x;
    const int NCH = BATCH * OUT_DIM;

#pragma unroll 10
    for (int t = 0; t < T_STEPS; t++)
        su[t * 256 + tid] = g_u2[(size_t)t * NCH + c0 + tid];
    __syncthreads();

    float mem = 0.0f;
#pragma unroll 10
    for (int t = 0; t < T_STEPS; t++) {
        float u = su[t * 256 + tid];
        mem = mem * DECAY_F + u;
        float sp = (mem >= THRESH_F) ? 1.0f : 0.0f;
        mem -= sp * THRESH_F;
        Odst[(size_t)t * NCH + c0 + tid] = sp;
    }
}

// ---------------------------------------------------------------------------
// Launch. gemm stays at launch #4 (ncu capture slot).
// ---------------------------------------------------------------------------
extern "C" void kernel_launch(void* const* d_in, const int* in_sizes, int n_in,
                              void* d_out, int out_size)
{
    const float* X  = (const float*)d_in[0];
    const float* W1 = (const float*)d_in[1];
    const float* W2 = (const float*)d_in[2];
    float* out = (float*)d_out;

    const long long TBH = (long long)T_STEPS * BATCH * HID_DIM;
    const long long TBO = (long long)T_STEPS * BATCH * OUT_DIM;

    float* hid_dst;
    float* out_dst;
    if ((long long)out_size == TBH + TBO) {
        hid_dst = out; out_dst = out + TBH;
    } else if ((long long)out_size == TBO) {
        void* p = nullptr; cudaGetSymbolAddress(&p, g_s1);
        hid_dst = (float*)p; out_dst = out;
    } else {
        hid_dst = out;
        void* p = nullptr; cudaGetSymbolAddress(&p, g_s1);
        out_dst = (float*)p;
    }

    cudaFuncSetAttribute(gemm1_kernel,
                         cudaFuncAttributeMaxDynamicSharedMemorySize, SMEM_GEMM);
    cudaFuncSetAttribute(lif2_kernel,
                         cudaFuncAttributeMaxDynamicSharedMemorySize, 256 * T_STEPS * 4);

    // 1) pack X as A-fragments
    {
        int n = KT_TILES * MT_TILES * 32;
        conv_x_kernel<<<(n + 255) / 256, 256>>>(X);
    }
    // 2) zero u2
    zero_kernel<<<(M_ROWS * OUT_DIM / 4 + 255) / 256, 256>>>();
    // 3) split + pack W as B-fragments
    {
        int n = KT_TILES * NT_TILES * 32;
        conv_w_kernel<<<(n + 255) / 256, 256>>>(W1);
    }
    // 4) GEMM (ncu capture slot)
    {
        dim3 grid(HID_DIM / 256, M_ROWS / 128);    // (4, 200)
        gemm1_kernel<<<grid, 512, SMEM_GEMM>>>();
    }
    // 5) hidden LIF scan + fused spike scatter
    lif1_kernel<<<BATCH * HID_DIM / 4 / 256, 256>>>(hid_dst, W2);
    // 6) output LIF scan
    lif2_kernel<<<BATCH * OUT_DIM / 256, 256, 256 * T_STEPS * 4>>>(out_dst);
}

// round 16
// speedup vs baseline: 1.1445x; 1.1445x over previous
#include <cuda_runtime.h>
#include <cuda_bf16.h>
#include <cstdint>

// ---------------------------------------------------------------------------
// SNN MLP forward — bf16 HMMA, fragment-prepacked, 2-CTA/SM GEMM.
//   Xb  = bf16(X)    binary -> exact, prepacked m16n8k16 A-fragment order
//   W1  = W1hi+W1lo  bf16 split (validated), prepacked B-fragment order
//   U1  = Xb@W1hi + Xb@W1lo   mma.sync m16n8k16, shared fp32 accumulators
//   S1  = LIF-scan(U1) + fused rare-spike scatter into U2
//   S2  = LIF-scan(U2) smem-staged
// R14/R15 ncu: tensor stuck ~60% at BOTH 2 and 4 warps/SMSP -> not warp-level
// latency; every config ran 1 CTA/SM so barriers idle the whole SM.
// Fix: BN=128, 256thr, launch_bounds(256,2) -> 2 CTAs/SM; single-sync pipeline.
// ---------------------------------------------------------------------------

#define T_STEPS  100
#define BATCH    256
#define IN_DIM   784
#define HID_DIM  1024
#define OUT_DIM  10
#define M_ROWS   25600
#define KT_TILES 50                  // K padded 784 -> 800 (49 real + 1 zero tile)
#define MT_TILES 1600
#define NT_TILES 128
#define DECAY_F  0.6f
#define THRESH_F 0.9f

// GEMM: BM=128, BN=128, BK=32 (2 k16/stage), 3 stages, 256 thr (8 warps 2m x 4n)
#define NIT      25
#define SA_OFF   0                   // A:  8KB
#define SBH_OFF  8192                // Bh: 8KB
#define SBL_OFF  16384               // Bl: 8KB
#define STAGE_BYTES 24576
#define SMEM_GEMM (3 * STAGE_BYTES)  // 73728 (x2 CTAs = 144KB/SM)

// Device scratch
__device__ float g_u1[(size_t)M_ROWS * HID_DIM];
__device__ float g_u2[(size_t)M_ROWS * OUT_DIM];
__device__ float g_s1[(size_t)M_ROWS * HID_DIM];
__device__ __align__(16) uint8_t g_xa[(size_t)KT_TILES * MT_TILES * 512];
__device__ __align__(16) uint8_t g_wh[(size_t)KT_TILES * NT_TILES * 256];
__device__ __align__(16) uint8_t g_wl[(size_t)KT_TILES * NT_TILES * 256];

// ---------------------------------------------------------------------------
// PTX helpers (sm_80-era only)
// ---------------------------------------------------------------------------
__device__ __forceinline__ uint32_t smem_u32(const void* p) {
    uint32_t a;
    asm("{ .reg .u64 t; cvta.to.shared.u64 t, %1; cvt.u32.u64 %0, t; }" : "=r"(a) : "l"(p));
    return a;
}
__device__ __forceinline__ void cp16(uint32_t dst, const void* src) {
    asm volatile("cp.async.cg.shared.global [%0], [%1], 16;" :: "r"(dst), "l"(src));
}
__device__ __forceinline__ void cp_commit() { asm volatile("cp.async.commit_group;" ::: "memory"); }
__device__ __forceinline__ void cp_wait1()  { asm volatile("cp.async.wait_group 1;"  ::: "memory"); }

__device__ __forceinline__ void lds128(uint32_t* r, uint32_t a) {
    asm volatile("ld.shared.v4.u32 {%0,%1,%2,%3}, [%4];"
                 : "=r"(r[0]), "=r"(r[1]), "=r"(r[2]), "=r"(r[3]) : "r"(a));
}
__device__ __forceinline__ void lds64(uint32_t* r, uint32_t a) {
    asm volatile("ld.shared.v2.u32 {%0,%1}, [%2];" : "=r"(r[0]), "=r"(r[1]) : "r"(a));
}
__device__ __forceinline__ void mma_bf16(float* c, const uint32_t* a, uint32_t b0, uint32_t b1) {
    asm volatile("mma.sync.aligned.m16n8k16.row.col.f32.bf16.bf16.f32 "
                 "{%0,%1,%2,%3}, {%4,%5,%6,%7}, {%8,%9}, {%0,%1,%2,%3};"
                 : "+f"(c[0]), "+f"(c[1]), "+f"(c[2]), "+f"(c[3])
                 : "r"(a[0]), "r"(a[1]), "r"(a[2]), "r"(a[3]), "r"(b0), "r"(b1));
}
__device__ __forceinline__ uint32_t bf16x2(float x, float y) {
    __nv_bfloat162 v = __float22bfloat162_rn(make_float2(x, y));
    return *reinterpret_cast<uint32_t*>(&v);
}

// ---------------------------------------------------------------------------
// conv_x: smem-staged, coalesced. One block per mt (16-row strip).
// Phase 1: coalesced float4 reads of X rows -> bf16 in smem (cols 784..799 = 0).
// Phase 2: emit A-fragments (tile 512B; lane 16B = a0..a3), coalesced uint4.
// ---------------------------------------------------------------------------
__global__ void conv_x_kernel(const float* __restrict__ X)
{
    __shared__ __align__(16) __nv_bfloat16 su[16][800];
    const int mt  = blockIdx.x;
    const int tid = threadIdx.x;

    for (int i = tid; i < 16 * 196; i += 256) {          // 784/4 = 196 float4 per row
        int r = i / 196, c4 = i - r * 196;
        float4 v = *reinterpret_cast<const float4*>(
            X + (size_t)(mt * 16 + r) * IN_DIM + c4 * 4);
        *reinterpret_cast<__nv_bfloat162*>(&su[r][c4 * 4]) =
            __float22bfloat162_rn(make_float2(v.x, v.y));
        *reinterpret_cast<__nv_bfloat162*>(&su[r][c4 * 4 + 2]) =
            __float22bfloat162_rn(make_float2(v.z, v.w));
    }
    if (tid < 128) {                                      // zero pad 16 rows x 16 cols
        int r = tid >> 3, c = 784 + (tid & 7) * 2;
        *reinterpret_cast<__nv_bfloat162*>(&su[r][c]) =
            __float22bfloat162_rn(make_float2(0.f, 0.f));
    }
    __syncthreads();

    const int w = tid >> 5, lane = tid & 31;
    const int r = lane >> 2;
    for (int kt = w; kt < KT_TILES; kt += 8) {
        int c = kt * 16 + 2 * (lane & 3);
        uint32_t a0 = *reinterpret_cast<const uint32_t*>(&su[r][c]);
        uint32_t a1 = *reinterpret_cast<const uint32_t*>(&su[r + 8][c]);
        uint32_t a2 = *reinterpret_cast<const uint32_t*>(&su[r][c + 8]);
        uint32_t a3 = *reinterpret_cast<const uint32_t*>(&su[r + 8][c + 8]);
        *reinterpret_cast<uint4*>(
            &g_xa[(((size_t)kt * MT_TILES + mt) * 32 + lane) * 16]) =
            make_uint4(a0, a1, a2, a3);
    }
}

__global__ void zero_kernel()
{
    int idx = blockIdx.x * blockDim.x + threadIdx.x;
    if (idx < M_ROWS * OUT_DIM / 4)
        reinterpret_cast<float4*>(g_u2)[idx] = make_float4(0.f, 0.f, 0.f, 0.f);
}

// ---------------------------------------------------------------------------
// conv_w: W1 -> hi/lo bf16 B-fragments (tile 256B; lane 8B = b0,b1)
// ---------------------------------------------------------------------------
__global__ void conv_w_kernel(const float* __restrict__ W1)
{
    int t = blockIdx.x * blockDim.x + threadIdx.x;
    if (t >= KT_TILES * NT_TILES * 32) return;
    int lane = t & 31;
    int tile = t >> 5;
    int kt = tile >> 7;
    int nt = tile & 127;

    int n = nt * 8 + (lane >> 2);
    int k = kt * 16 + 2 * (lane & 3);

    float w[4];
#pragma unroll
    for (int j = 0; j < 4; j++) {
        int kk = k + (j >> 1) * 8 + (j & 1);          // k, k+1, k+8, k+9
        w[j] = (kk < IN_DIM) ? W1[(size_t)kk * HID_DIM + n] : 0.f;
    }
    float hi[4], lo[4];
#pragma unroll
    for (int j = 0; j < 4; j++) {
        hi[j] = __bfloat162float(__float2bfloat16_rn(w[j]));
        lo[j] = w[j] - hi[j];
    }
    *reinterpret_cast<uint2*>(&g_wh[(size_t)t * 8]) =
        make_uint2(bf16x2(hi[0], hi[1]), bf16x2(hi[2], hi[3]));
    *reinterpret_cast<uint2*>(&g_wl[(size_t)t * 8]) =
        make_uint2(bf16x2(lo[0], lo[1]), bf16x2(lo[2], lo[3]));
}

// ---------------------------------------------------------------------------
// GEMM1: 256 thr, 8 warps (2m x 4n), warp 64x32; BM=128 BN=128 BK=32;
// 3 stages, single __syncthreads per iteration, 2 CTAs/SM.
// ---------------------------------------------------------------------------
__global__ void __launch_bounds__(256, 2)
gemm1_kernel()
{
    extern __shared__ char smem[];
    const uint32_t sb = smem_u32(smem);
    const int tid  = threadIdx.x;
    const int lane = tid & 31;
    const int w    = tid >> 5;
    const int wm   = w >> 2;           // 0..1  (m: 64 rows)
    const int wn   = w & 3;            // 0..3  (n: 32 cols)
    const int bx   = blockIdx.x;       // 0..7
    const int by   = blockIdx.y;       // 0..199

    auto load_stage = [&](int it, int s) {
        uint32_t st = sb + (uint32_t)s * STAGE_BYTES;
        // A: 8KB = 512 cp16 -> 2 per thread
#pragma unroll
        for (int h = 0; h < 2; h++) {
            int id  = tid + h * 256;               // 0..511
            int ktl = id >> 8;
            int rem = id & 255;                    // mt_local*32 + lane
            cp16(st + SA_OFF + (uint32_t)id * 16,
                 g_xa + ((size_t)(it * 2 + ktl) * MT_TILES + by * 8 + (rem >> 5)) * 512
                      + (rem & 31) * 16);
        }
        // B planes: 8KB each = 512 cp16 -> 2 per thread per plane
#pragma unroll
        for (int h = 0; h < 2; h++) {
            int id  = tid + h * 256;               // 0..511
            int ktl = id >> 8;
            int rem = id & 255;                    // nt_local*16 + chunk
            size_t src = ((size_t)(it * 2 + ktl) * NT_TILES + bx * 16 + (rem >> 4)) * 256
                         + (rem & 15) * 16;
            uint32_t dst = (uint32_t)id * 16;
            cp16(st + SBH_OFF + dst, g_wh + src);
            cp16(st + SBL_OFF + dst, g_wl + src);
        }
    };

    float acc[4][4][4];
#pragma unroll
    for (int i = 0; i < 4; i++)
#pragma unroll
        for (int j = 0; j < 4; j++)
#pragma unroll
            for (int q = 0; q < 4; q++) acc[i][j][q] = 0.f;

    load_stage(0, 0); cp_commit();
    load_stage(1, 1); cp_commit();

    for (int it = 0; it < NIT; it++) {
        cp_wait1();                                // my group g_it complete
        __syncthreads();                           // visibility + all warps done reading
                                                   // the stage about to be overwritten
        const uint32_t st = sb + (uint32_t)(it % 3) * STAGE_BYTES;
#pragma unroll
        for (int ktl = 0; ktl < 2; ktl++) {
            uint32_t a[4][4];
#pragma unroll
            for (int i = 0; i < 4; i++)
                lds128(a[i], st + SA_OFF +
                       (uint32_t)(ktl * 4096 + (wm * 4 + i) * 512 + lane * 16));
#pragma unroll
            for (int j = 0; j < 4; j++) {          // hi plane
                uint32_t b[2];
                lds64(b, st + SBH_OFF +
                      (uint32_t)(ktl * 4096 + (wn * 4 + j) * 256 + lane * 8));
#pragma unroll
                for (int i = 0; i < 4; i++) mma_bf16(acc[i][j], a[i], b[0], b[1]);
            }
#pragma unroll
            for (int j = 0; j < 4; j++) {          // lo plane, same accumulators
                uint32_t b[2];
                lds64(b, st + SBL_OFF +
                      (uint32_t)(ktl * 4096 + (wn * 4 + j) * 256 + lane * 8));
#pragma unroll
                for (int i = 0; i < 4; i++) mma_bf16(acc[i][j], a[i], b[0], b[1]);
            }
        }
        if (it + 2 < NIT) load_stage(it + 2, (it + 2) % 3);
        cp_commit();                               // tail empty groups keep count aligned
    }

    // Epilogue
    const int row0 = by * 128 + wm * 64 + (lane >> 2);
    const int col0 = bx * 128 + wn * 32 + 2 * (lane & 3);
#pragma unroll
    for (int i = 0; i < 4; i++) {
#pragma unroll
        for (int j = 0; j < 4; j++) {
            float* p0 = g_u1 + (size_t)(row0 + i * 16)     * HID_DIM + col0 + j * 8;
            float* p1 = g_u1 + (size_t)(row0 + i * 16 + 8) * HID_DIM + col0 + j * 8;
            *reinterpret_cast<float2*>(p0) = make_float2(acc[i][j][0], acc[i][j][1]);
            *reinterpret_cast<float2*>(p1) = make_float2(acc[i][j][2], acc[i][j][3]);
        }
    }
}

// ---------------------------------------------------------------------------
// lif1 (float4, 4 chains/thread) + fused rare-spike scatter into U2
// ---------------------------------------------------------------------------
__global__ void lif1_kernel(float* __restrict__ Sdst, const float* __restrict__ W2)
{
    const int t4 = (blockIdx.x * blockDim.x + threadIdx.x) * 4;
    if (t4 >= BATCH * HID_DIM) return;
    const int b  = t4 >> 10;
    const int h0 = t4 & 1023;
    const size_t stride = (size_t)BATCH * HID_DIM;

    float m0 = 0.f, m1 = 0.f, m2 = 0.f, m3 = 0.f;
    for (int t = 0; t < T_STEPS; t++) {
        float4 u = *reinterpret_cast<const float4*>(g_u1 + (size_t)t * stride + t4);
        m0 = m0 * DECAY_F + u.x;  m1 = m1 * DECAY_F + u.y;
        m2 = m2 * DECAY_F + u.z;  m3 = m3 * DECAY_F + u.w;
        float s0 = (m0 >= THRESH_F) ? 1.f : 0.f;
        float s1 = (m1 >= THRESH_F) ? 1.f : 0.f;
        float s2 = (m2 >= THRESH_F) ? 1.f : 0.f;
        float s3 = (m3 >= THRESH_F) ? 1.f : 0.f;
        m0 -= s0 * THRESH_F; m1 -= s1 * THRESH_F;
        m2 -= s2 * THRESH_F; m3 -= s3 * THRESH_F;
        *reinterpret_cast<float4*>(Sdst + (size_t)t * stride + t4) =
            make_float4(s0, s1, s2, s3);
        if (s0 + s1 + s2 + s3 != 0.f) {            // rare path
            float* u2 = g_u2 + (size_t)t * BATCH * OUT_DIM + (size_t)b * OUT_DIM;
            float sv[4] = {s0, s1, s2, s3};
#pragma unroll
            for (int c = 0; c < 4; c++) {
                if (sv[c] != 0.f) {
                    const float* wr = W2 + (size_t)(h0 + c) * OUT_DIM;
#pragma unroll
                    for (int o = 0; o < OUT_DIM; o++) atomicAdd(u2 + o, wr[o]);
                }
            }
        }
    }
}

// ---------------------------------------------------------------------------
// lif2: smem-staged scan
// ---------------------------------------------------------------------------
__global__ void lif2_kernel(float* __restrict__ Odst)
{
    extern __shared__ float su2[];
    const int c0 = blockIdx.x * 256;
    const int tid = threadIdx.x;
    const int NCH = BATCH * OUT_DIM;

#pragma unroll 10
    for (int t = 0; t < T_STEPS; t++)
        su2[t * 256 + tid] = g_u2[(size_t)t * NCH + c0 + tid];
    __syncthreads();

    float mem = 0.0f;
#pragma unroll 10
    for (int t = 0; t < T_STEPS; t++) {
        float u = su2[t * 256 + tid];
        mem = mem * DECAY_F + u;
        float sp = (mem >= THRESH_F) ? 1.0f : 0.0f;
        mem -= sp * THRESH_F;
        Odst[(size_t)t * NCH + c0 + tid] = sp;
    }
}

// ---------------------------------------------------------------------------
// Launch. gemm stays at launch #4 (ncu capture slot).
// ---------------------------------------------------------------------------
extern "C" void kernel_launch(void* const* d_in, const int* in_sizes, int n_in,
                              void* d_out, int out_size)
{
    const float* X  = (const float*)d_in[0];
    const float* W1 = (const float*)d_in[1];
    const float* W2 = (const float*)d_in[2];
    float* out = (float*)d_out;

    const long long TBH = (long long)T_STEPS * BATCH * HID_DIM;
    const long long TBO = (long long)T_STEPS * BATCH * OUT_DIM;

    float* hid_dst;
    float* out_dst;
    if ((long long)out_size == TBH + TBO) {
        hid_dst = out; out_dst = out + TBH;
    } else if ((long long)out_size == TBO) {
        void* p = nullptr; cudaGetSymbolAddress(&p, g_s1);
        hid_dst = (float*)p; out_dst = out;
    } else {
        hid_dst = out;
        void* p = nullptr; cudaGetSymbolAddress(&p, g_s1);
        out_dst = (float*)p;
    }

    cudaFuncSetAttribute(gemm1_kernel,
                         cudaFuncAttributeMaxDynamicSharedMemorySize, SMEM_GEMM);
    cudaFuncSetAttribute(lif2_kernel,
                         cudaFuncAttributeMaxDynamicSharedMemorySize, 256 * T_STEPS * 4);

    // 1) pack X as A-fragments (coalesced, smem-staged)
    conv_x_kernel<<<MT_TILES, 256>>>(X);
    // 2) zero u2
    zero_kernel<<<(M_ROWS * OUT_DIM / 4 + 255) / 256, 256>>>();
    // 3) split + pack W as B-fragments
    {
        int n = KT_TILES * NT_TILES * 32;
        conv_w_kernel<<<(n + 255) / 256, 256>>>(W1);
    }
    // 4) GEMM (ncu capture slot) — 2 CTAs/SM
    {
        dim3 grid(HID_DIM / 128, M_ROWS / 128);    // (8, 200)
        gemm1_kernel<<<grid, 256, SMEM_GEMM>>>();
    }
    // 5) hidden LIF scan + fused spike scatter
    lif1_kernel<<<BATCH * HID_DIM / 4 / 256, 256>>>(hid_dst, W2);
    // 6) output LIF scan
    lif2_kernel<<<BATCH * OUT_DIM / 256, 256, 256 * T_STEPS * 4>>>(out_dst);
}